// round 14
// baseline (speedup 1.0000x reference)
#include <cuda_runtime.h>

#define NN    50000
#define DIN   128
#define DOUT  64
#define EE    800000
#define GTILE 64          // nodes per GEMM block
#define SHPAD 132         // padded sH row stride (breaks bank conflicts)
#define NB    296         // persistent CSR kernel blocks (2/SM, all co-resident)
#define NBS   196         // scan chunks of 256 nodes (196*256 >= NN)

// ---------------------------------------------------------------------------
// Device scratch
// ---------------------------------------------------------------------------
__device__ float  g_X[NN * DOUT];     // projected features
__device__ int    g_cnt[NN];          // degree counters (zero between calls)
__device__ int    g_cur[NN];          // scatter cursors
__device__ int    g_rowptr[NN + 1];   // CSR row offsets
__device__ int    g_scan[NN];         // block-local exclusive scan
__device__ int    g_bsum[NBS];        // per-chunk totals
__device__ float2 g_edge[EE];         // CSR (col as int bits, val)

// software grid barrier state (monotonic generation counter)
__device__ volatile int g_barflag;
__device__ int          g_barcnt;

// ---------------------------------------------------------------------------
// Grid barrier: every one of NB blocks must arrive before release.
// Generation targets are absolute (base read at kernel entry is safe: the
// flag cannot advance past base until ALL blocks have arrived at barrier 1).
// ---------------------------------------------------------------------------
__device__ __forceinline__ void grid_barrier(int target) {
    __syncthreads();
    if (threadIdx.x == 0) {
        __threadfence();
        if (atomicAdd(&g_barcnt, 1) == NB - 1) {
            atomicExch(&g_barcnt, 0);
            __threadfence();
            g_barflag = target;
        } else {
            while (g_barflag < target) __nanosleep(32);
        }
        __threadfence();
    }
    __syncthreads();
}

// ---------------------------------------------------------------------------
// Persistent CSR build: hist -> scan(+zero) -> offsets/cursors -> scatter
// ---------------------------------------------------------------------------
__global__ __launch_bounds__(256) void csr_build_kernel(
    const int*   __restrict__ rows,
    const int*   __restrict__ cols,
    const float* __restrict__ vals)
{
    __shared__ int sdata[256];
    __shared__ int sOff[256];

    const int tid = threadIdx.x;
    const int blk = blockIdx.x;
    const int gstride = NB * 256;
    const int gtid = blk * 256 + tid;

    // generation base: stable between calls (no writers active at entry)
    int base = g_barflag;

    // ---- phase 1: histogram (g_cnt starts all-zero) ----
    for (int e = gtid; e < EE; e += gstride)
        atomicAdd(&g_cnt[rows[e]], 1);

    grid_barrier(base + 1);

    // ---- phase 2: per-chunk scan; read-and-zero g_cnt ----
    if (blk < NBS) {
        int i = blk * 256 + tid;
        int val = (i < NN) ? g_cnt[i] : 0;
        if (i < NN) g_cnt[i] = 0;          // restore invariant for next call
        sdata[tid] = val;
        __syncthreads();
        #pragma unroll
        for (int off = 1; off < 256; off <<= 1) {
            int v = (tid >= off) ? sdata[tid - off] : 0;
            __syncthreads();
            sdata[tid] += v;
            __syncthreads();
        }
        if (i < NN) g_scan[i] = sdata[tid] - val;
        if (tid == 255) g_bsum[blk] = sdata[255];
    }

    grid_barrier(base + 2);

    // ---- phase 3: redundant scan of chunk totals; finalize rowptr/cursors ----
    {
        int v = (tid < NBS) ? g_bsum[tid] : 0;
        sdata[tid] = v;
        __syncthreads();
        #pragma unroll
        for (int off = 1; off < 256; off <<= 1) {
            int x = (tid >= off) ? sdata[tid - off] : 0;
            __syncthreads();
            sdata[tid] += x;
            __syncthreads();
        }
        sOff[tid] = sdata[tid] - v;        // exclusive prefix of chunk totals
        __syncthreads();
    }
    if (blk < NBS) {
        int i = blk * 256 + tid;
        if (i < NN) {
            int r = g_scan[i] + sOff[blk];
            g_rowptr[i] = r;
            g_cur[i]    = r;
        }
    }
    if (gtid == 0) g_rowptr[NN] = EE;

    grid_barrier(base + 3);

    // ---- phase 4: scatter edges into CSR order (packed 8B records) ----
    for (int e = gtid; e < EE; e += gstride) {
        int pos = atomicAdd(&g_cur[rows[e]], 1);
        g_edge[pos] = make_float2(__int_as_float(cols[e]), vals[e]);
    }
}

// ---------------------------------------------------------------------------
// Fused L2-normalize + BN(eval) + Linear(128->64)+bias -> g_X
//   R5-proven scalar version: 64 nodes / block, 128 threads,
//   each thread 8 nodes x 4 cols. smem ~66 KB -> 3 CTAs/SM.
// ---------------------------------------------------------------------------
__global__ __launch_bounds__(128) void fused_gemm_kernel(
    const float* __restrict__ H,
    const float* __restrict__ gamma,
    const float* __restrict__ beta,
    const float* __restrict__ mean,
    const float* __restrict__ var,
    const float* __restrict__ W,
    const float* __restrict__ bias)
{
    __shared__ float sW[DIN * DOUT];        // 32 KB
    __shared__ float sH[GTILE * SHPAD];     // 33.8 KB
    __shared__ float sA[DIN];
    __shared__ float sC[DIN];
    __shared__ float sInv[GTILE];

    const int tid    = threadIdx.x;
    const int node0  = blockIdx.x * GTILE;
    const int nvalid = min(GTILE, NN - node0);

    #pragma unroll
    for (int i = tid; i < DIN * DOUT / 4; i += 128)
        reinterpret_cast<float4*>(sW)[i] =
            reinterpret_cast<const float4*>(W)[i];

    {
        float a = gamma[tid] * rsqrtf(var[tid] + 1e-5f);
        sA[tid] = a;
        sC[tid] = beta[tid] - mean[tid] * a;
    }

    #pragma unroll
    for (int i4 = tid; i4 < GTILE * (DIN / 4); i4 += 128) {
        int r = i4 >> 5;
        int c = (i4 & 31) * 4;
        float4 v = (r < nvalid)
            ? reinterpret_cast<const float4*>(H)[(node0 + r) * (DIN / 4) + (c >> 2)]
            : make_float4(1.f, 0.f, 0.f, 0.f);
        *reinterpret_cast<float4*>(&sH[r * SHPAD + c]) = v;
    }
    __syncthreads();

    {
        int r = tid >> 1, l = tid & 1;
        float ss = 0.f;
        #pragma unroll
        for (int i = 0; i < 16; i++) {
            float4 v = *reinterpret_cast<float4*>(&sH[r * SHPAD + l * 64 + i * 4]);
            ss += v.x * v.x + v.y * v.y + v.z * v.z + v.w * v.w;
        }
        ss += __shfl_xor_sync(0xffffffffu, ss, 1);
        if (l == 0) sInv[r] = 1.0f / fmaxf(sqrtf(ss), 1e-12f);
    }
    __syncthreads();

    #pragma unroll
    for (int i4 = tid; i4 < GTILE * (DIN / 4); i4 += 128) {
        int r = i4 >> 5;
        int c = (i4 & 31) * 4;
        float inv = sInv[r];
        float4 h  = *reinterpret_cast<float4*>(&sH[r * SHPAD + c]);
        float4 a  = *reinterpret_cast<float4*>(&sA[c]);
        float4 cc = *reinterpret_cast<float4*>(&sC[c]);
        h.x = fmaf(h.x * inv, a.x, cc.x);
        h.y = fmaf(h.y * inv, a.y, cc.y);
        h.z = fmaf(h.z * inv, a.z, cc.z);
        h.w = fmaf(h.w * inv, a.w, cc.w);
        *reinterpret_cast<float4*>(&sH[r * SHPAD + c]) = h;
    }
    __syncthreads();

    const int jg = tid & 15;
    const int ng = tid >> 4;
    const int n0 = ng * 8;
    const int j0 = jg * 4;

    float4 acc[8];
    #pragma unroll
    for (int i = 0; i < 8; i++) acc[i] = make_float4(0.f, 0.f, 0.f, 0.f);

    #pragma unroll 4
    for (int k = 0; k < DIN; k++) {
        float4 w = *reinterpret_cast<float4*>(&sW[k * DOUT + j0]);
        #pragma unroll
        for (int i = 0; i < 8; i++) {
            float h = sH[(n0 + i) * SHPAD + k];
            acc[i].x = fmaf(h, w.x, acc[i].x);
            acc[i].y = fmaf(h, w.y, acc[i].y);
            acc[i].z = fmaf(h, w.z, acc[i].z);
            acc[i].w = fmaf(h, w.w, acc[i].w);
        }
    }

    float4 bb = *reinterpret_cast<const float4*>(&bias[j0]);
    #pragma unroll
    for (int i = 0; i < 8; i++) {
        if (n0 + i < nvalid) {
            float4 a = acc[i];
            a.x += bb.x; a.y += bb.y; a.z += bb.z; a.w += bb.w;
            *reinterpret_cast<float4*>(&g_X[(node0 + n0 + i) * DOUT + j0]) = a;
        }
    }
}

// ---------------------------------------------------------------------------
// Row-parallel SpMM + LeakyReLU: 16 threads per row, float4 per lane
// ---------------------------------------------------------------------------
__global__ __launch_bounds__(256) void spmm_leaky_kernel(float* __restrict__ out)
{
    int gid  = blockIdx.x * 256 + threadIdx.x;
    int row  = gid >> 4;
    if (row >= NN) return;
    int lane = gid & 15;
    int c0   = lane * 4;

    int s = g_rowptr[row];
    int e = g_rowptr[row + 1];

    float4 a = make_float4(0.f, 0.f, 0.f, 0.f);

    for (int p = s; p < e; ++p) {
        float2 ev = g_edge[p];
        int   col = __float_as_int(ev.x);
        float v   = ev.y;
        float4 x  = *reinterpret_cast<const float4*>(&g_X[col * DOUT + c0]);
        a.x = fmaf(v, x.x, a.x);
        a.y = fmaf(v, x.y, a.y);
        a.z = fmaf(v, x.z, a.z);
        a.w = fmaf(v, x.w, a.w);
    }

    a.x = a.x >= 0.f ? a.x : 0.01f * a.x;
    a.y = a.y >= 0.f ? a.y : 0.01f * a.y;
    a.z = a.z >= 0.f ? a.z : 0.01f * a.z;
    a.w = a.w >= 0.f ? a.w : 0.01f * a.w;

    *reinterpret_cast<float4*>(&out[row * DOUT + c0]) = a;
}

// ---------------------------------------------------------------------------
// Launch: 3 graph nodes. CSR (persistent) and GEMM run as parallel roots;
// SpMM joins both.
// ---------------------------------------------------------------------------
extern "C" void kernel_launch(void* const* d_in, const int* in_sizes, int n_in,
                              void* d_out, int out_size) {
    const float* H     = (const float*)d_in[0];
    const int*   rows  = (const int*)  d_in[1];
    const int*   cols  = (const int*)  d_in[2];
    const float* vals  = (const float*)d_in[3];
    const float* gamma = (const float*)d_in[4];
    const float* beta  = (const float*)d_in[5];
    const float* rmean = (const float*)d_in[6];
    const float* rvar  = (const float*)d_in[7];
    const float* W     = (const float*)d_in[8];
    const float* b     = (const float*)d_in[9];
    float* out = (float*)d_out;

    cudaStream_t s0 = 0;
    cudaStream_t s1;
    cudaEvent_t  evFork, evJoin;
    cudaStreamCreateWithFlags(&s1, cudaStreamNonBlocking);
    cudaEventCreateWithFlags(&evFork, cudaEventDisableTiming);
    cudaEventCreateWithFlags(&evJoin, cudaEventDisableTiming);

    // CSR build launched first so its 296 blocks claim residency slots first.
    csr_build_kernel<<<NB, 256, 0, s0>>>(rows, cols, vals);

    // GEMM as parallel root on s1
    cudaEventRecord(evFork, s0);   // after csr launch; GEMM may still overlap it
    cudaStreamWaitEvent(s1, evFork, 0);
    fused_gemm_kernel<<<(NN + GTILE - 1) / GTILE, 128, 0, s1>>>(
        H, gamma, beta, rmean, rvar, W, b);
    cudaEventRecord(evJoin, s1);

    // SpMM joins both chains
    cudaStreamWaitEvent(s0, evJoin, 0);
    spmm_leaky_kernel<<<(NN * 16 + 255) / 256, 256, 0, s0>>>(out);

    cudaEventDestroy(evFork);
    cudaEventDestroy(evJoin);
    cudaStreamDestroy(s1);
}

// round 15
// speedup vs baseline: 1.1183x; 1.1183x over previous
#include <cuda_runtime.h>

#define NN    50000
#define DIN   128
#define DOUT  64
#define EE    800000
#define GTILE 64          // nodes per GEMM block
#define SHPAD 132         // padded sH row stride (breaks bank conflicts)
#define NB1   49          // scan1 blocks (49*1024 >= NN)

// ---------------------------------------------------------------------------
// Device scratch
// ---------------------------------------------------------------------------
__device__ float  g_X[NN * DOUT];     // projected features
__device__ int    g_cnt[NN];          // degree counters -> scatter cursors
__device__ int    g_rowptr[NN + 1];   // CSR row offsets
__device__ int    g_scan[NN];         // block-local exclusive scan
__device__ int    g_bsum[NB1];        // per-block totals
__device__ float2 g_edge[EE];         // CSR (col as int bits, val)

// ---------------------------------------------------------------------------
// CSR build (R12-proven forms)
// ---------------------------------------------------------------------------
__global__ void zero_cnt_kernel() {
    int i = blockIdx.x * blockDim.x + threadIdx.x;
    if (i < NN) g_cnt[i] = 0;
}

__global__ void hist_kernel(const int* __restrict__ rows) {
    int e = blockIdx.x * blockDim.x + threadIdx.x;
    if (e < EE) atomicAdd(&g_cnt[rows[e]], 1);
}

__global__ __launch_bounds__(1024) void scan1_kernel() {
    __shared__ int wsum[32];
    int tid  = threadIdx.x;
    int i    = blockIdx.x * 1024 + tid;
    int lane = tid & 31, warp = tid >> 5;

    int orig = (i < NN) ? g_cnt[i] : 0;
    int v = orig;
    #pragma unroll
    for (int o = 1; o < 32; o <<= 1) {
        int n = __shfl_up_sync(0xffffffffu, v, o);
        if (lane >= o) v += n;
    }
    if (lane == 31) wsum[warp] = v;
    __syncthreads();
    if (warp == 0) {
        int s = wsum[lane];
        #pragma unroll
        for (int o = 1; o < 32; o <<= 1) {
            int n = __shfl_up_sync(0xffffffffu, s, o);
            if (lane >= o) s += n;
        }
        wsum[lane] = s;
    }
    __syncthreads();
    int base = (warp > 0) ? wsum[warp - 1] : 0;
    if (i < NN) g_scan[i] = base + v - orig;
    if (tid == 1023) g_bsum[blockIdx.x] = wsum[31];
}

__global__ __launch_bounds__(256) void scan3_kernel() {
    __shared__ int sOff[NB1];
    int tid = threadIdx.x;

    if (tid < 32) {
        int a = (2 * tid     < NB1) ? g_bsum[2 * tid]     : 0;
        int b = (2 * tid + 1 < NB1) ? g_bsum[2 * tid + 1] : 0;
        int s = a + b;
        int incl = s;
        #pragma unroll
        for (int o = 1; o < 32; o <<= 1) {
            int n = __shfl_up_sync(0xffffffffu, incl, o);
            if (tid >= o) incl += n;
        }
        int excl = incl - s;
        if (2 * tid     < NB1) sOff[2 * tid]     = excl;
        if (2 * tid + 1 < NB1) sOff[2 * tid + 1] = excl + a;
    }
    __syncthreads();

    int i = blockIdx.x * 256 + tid;
    if (i < NN) {
        int r = g_scan[i] + sOff[i >> 10];
        g_rowptr[i] = r;
        g_cnt[i]    = r;
    }
    if (i == 0) g_rowptr[NN] = EE;
}

__global__ void scatter_kernel(const int* __restrict__ rows,
                               const int* __restrict__ cols,
                               const float* __restrict__ vals) {
    int e = blockIdx.x * blockDim.x + threadIdx.x;
    if (e < EE) {
        int pos = atomicAdd(&g_cnt[rows[e]], 1);
        g_edge[pos] = make_float2(__int_as_float(cols[e]), vals[e]);
    }
}

// ---------------------------------------------------------------------------
// Fused L2-normalize + BN(eval) + Linear(128->64)+bias -> g_X  (R12-proven)
// ---------------------------------------------------------------------------
__global__ __launch_bounds__(128) void fused_gemm_kernel(
    const float* __restrict__ H,
    const float* __restrict__ gamma,
    const float* __restrict__ beta,
    const float* __restrict__ mean,
    const float* __restrict__ var,
    const float* __restrict__ W,
    const float* __restrict__ bias)
{
    __shared__ float sW[DIN * DOUT];
    __shared__ float sH[GTILE * SHPAD];
    __shared__ float sA[DIN];
    __shared__ float sC[DIN];
    __shared__ float sInv[GTILE];

    const int tid    = threadIdx.x;
    const int node0  = blockIdx.x * GTILE;
    const int nvalid = min(GTILE, NN - node0);

    #pragma unroll
    for (int i = tid; i < DIN * DOUT / 4; i += 128)
        reinterpret_cast<float4*>(sW)[i] =
            reinterpret_cast<const float4*>(W)[i];

    {
        float a = gamma[tid] * rsqrtf(var[tid] + 1e-5f);
        sA[tid] = a;
        sC[tid] = beta[tid] - mean[tid] * a;
    }

    #pragma unroll
    for (int i4 = tid; i4 < GTILE * (DIN / 4); i4 += 128) {
        int r = i4 >> 5;
        int c = (i4 & 31) * 4;
        float4 v = (r < nvalid)
            ? reinterpret_cast<const float4*>(H)[(node0 + r) * (DIN / 4) + (c >> 2)]
            : make_float4(1.f, 0.f, 0.f, 0.f);
        *reinterpret_cast<float4*>(&sH[r * SHPAD + c]) = v;
    }
    __syncthreads();

    {
        int r = tid >> 1, l = tid & 1;
        float ss = 0.f;
        #pragma unroll
        for (int i = 0; i < 16; i++) {
            float4 v = *reinterpret_cast<float4*>(&sH[r * SHPAD + l * 64 + i * 4]);
            ss += v.x * v.x + v.y * v.y + v.z * v.z + v.w * v.w;
        }
        ss += __shfl_xor_sync(0xffffffffu, ss, 1);
        if (l == 0) sInv[r] = 1.0f / fmaxf(sqrtf(ss), 1e-12f);
    }
    __syncthreads();

    #pragma unroll
    for (int i4 = tid; i4 < GTILE * (DIN / 4); i4 += 128) {
        int r = i4 >> 5;
        int c = (i4 & 31) * 4;
        float inv = sInv[r];
        float4 h  = *reinterpret_cast<float4*>(&sH[r * SHPAD + c]);
        float4 a  = *reinterpret_cast<float4*>(&sA[c]);
        float4 cc = *reinterpret_cast<float4*>(&sC[c]);
        h.x = fmaf(h.x * inv, a.x, cc.x);
        h.y = fmaf(h.y * inv, a.y, cc.y);
        h.z = fmaf(h.z * inv, a.z, cc.z);
        h.w = fmaf(h.w * inv, a.w, cc.w);
        *reinterpret_cast<float4*>(&sH[r * SHPAD + c]) = h;
    }
    __syncthreads();

    const int jg = tid & 15;
    const int ng = tid >> 4;
    const int n0 = ng * 8;
    const int j0 = jg * 4;

    float4 acc[8];
    #pragma unroll
    for (int i = 0; i < 8; i++) acc[i] = make_float4(0.f, 0.f, 0.f, 0.f);

    #pragma unroll 4
    for (int k = 0; k < DIN; k++) {
        float4 w = *reinterpret_cast<float4*>(&sW[k * DOUT + j0]);
        #pragma unroll
        for (int i = 0; i < 8; i++) {
            float h = sH[(n0 + i) * SHPAD + k];
            acc[i].x = fmaf(h, w.x, acc[i].x);
            acc[i].y = fmaf(h, w.y, acc[i].y);
            acc[i].z = fmaf(h, w.z, acc[i].z);
            acc[i].w = fmaf(h, w.w, acc[i].w);
        }
    }

    float4 bb = *reinterpret_cast<const float4*>(&bias[j0]);
    #pragma unroll
    for (int i = 0; i < 8; i++) {
        if (n0 + i < nvalid) {
            float4 a = acc[i];
            a.x += bb.x; a.y += bb.y; a.z += bb.z; a.w += bb.w;
            *reinterpret_cast<float4*>(&g_X[(node0 + n0 + i) * DOUT + j0]) = a;
        }
    }
}

// ---------------------------------------------------------------------------
// SpMM + LeakyReLU, MLP-restructured:
//   16 lanes per row. The 16 lanes cooperatively load up to 16 edge records
//   (one coalesced float2 each), then broadcast via shfl(width=16). All
//   (col,val) are register-resident before the X gathers, so the unroll-4
//   loop keeps multiple independent 256B-coalesced gathers in flight.
// ---------------------------------------------------------------------------
__global__ __launch_bounds__(256) void spmm_leaky_kernel(float* __restrict__ out)
{
    int gid  = blockIdx.x * 256 + threadIdx.x;
    int row  = gid >> 4;
    if (row >= NN) return;
    int sub  = gid & 15;          // lane within the 16-lane row group
    int c0   = sub * 4;

    int s = g_rowptr[row];
    int e = g_rowptr[row + 1];

    float4 a = make_float4(0.f, 0.f, 0.f, 0.f);

    for (int base = s; base < e; base += 16) {
        // batch-load up to 16 edge records, coalesced across the group
        int   ep = base + sub;
        float2 ev = (ep < e) ? g_edge[ep] : make_float2(__int_as_float(0), 0.f);
        int ci = __float_as_int(ev.x);
        int cnt = min(16, e - base);

        #pragma unroll 4
        for (int j = 0; j < cnt; j++) {
            int   col = __shfl_sync(0xffffffffu, ci,   j, 16);
            float v   = __shfl_sync(0xffffffffu, ev.y, j, 16);
            float4 x  = *reinterpret_cast<const float4*>(&g_X[col * DOUT + c0]);
            a.x = fmaf(v, x.x, a.x);
            a.y = fmaf(v, x.y, a.y);
            a.z = fmaf(v, x.z, a.z);
            a.w = fmaf(v, x.w, a.w);
        }
    }

    a.x = a.x >= 0.f ? a.x : 0.01f * a.x;
    a.y = a.y >= 0.f ? a.y : 0.01f * a.y;
    a.z = a.z >= 0.f ? a.z : 0.01f * a.z;
    a.w = a.w >= 0.f ? a.w : 0.01f * a.w;

    *reinterpret_cast<float4*>(&out[row * DOUT + c0]) = a;
}

// ---------------------------------------------------------------------------
// Launch: R12 structure — CSR chain on s0, GEMM forked on s1, SpMM joins.
// ---------------------------------------------------------------------------
extern "C" void kernel_launch(void* const* d_in, const int* in_sizes, int n_in,
                              void* d_out, int out_size) {
    const float* H     = (const float*)d_in[0];
    const int*   rows  = (const int*)  d_in[1];
    const int*   cols  = (const int*)  d_in[2];
    const float* vals  = (const float*)d_in[3];
    const float* gamma = (const float*)d_in[4];
    const float* beta  = (const float*)d_in[5];
    const float* rmean = (const float*)d_in[6];
    const float* rvar  = (const float*)d_in[7];
    const float* W     = (const float*)d_in[8];
    const float* b     = (const float*)d_in[9];
    float* out = (float*)d_out;

    cudaStream_t s0 = 0;
    cudaStream_t s1;
    cudaEvent_t  evFork, evJoin;
    cudaStreamCreateWithFlags(&s1, cudaStreamNonBlocking);
    cudaEventCreateWithFlags(&evFork, cudaEventDisableTiming);
    cudaEventCreateWithFlags(&evJoin, cudaEventDisableTiming);

    // Fork: GEMM chain on s1, independent of CSR build
    cudaEventRecord(evFork, s0);
    cudaStreamWaitEvent(s1, evFork, 0);
    fused_gemm_kernel<<<(NN + GTILE - 1) / GTILE, 128, 0, s1>>>(
        H, gamma, beta, rmean, rvar, W, b);
    cudaEventRecord(evJoin, s1);

    // CSR build chain on s0 (concurrent with GEMM)
    zero_cnt_kernel<<<(NN + 255) / 256, 256, 0, s0>>>();
    hist_kernel<<<(EE + 255) / 256, 256, 0, s0>>>(rows);
    scan1_kernel<<<NB1, 1024, 0, s0>>>();
    scan3_kernel<<<(NN + 255) / 256, 256, 0, s0>>>();
    scatter_kernel<<<(EE + 255) / 256, 256, 0, s0>>>(rows, cols, vals);

    // Join: SpMM needs both g_X (s1) and CSR arrays (s0)
    cudaStreamWaitEvent(s0, evJoin, 0);
    spmm_leaky_kernel<<<(NN * 16 + 255) / 256, 256, 0, s0>>>(out);

    cudaEventDestroy(evFork);
    cudaEventDestroy(evJoin);
    cudaStreamDestroy(s1);
}